// round 1
// baseline (speedup 1.0000x reference)
#include <cuda_runtime.h>

#define BB 64
#define SS 8192
#define DDIM 64
#define SPLIT 8
#define ROWS_P1 (SS / SPLIT)   // 1024 rows per phase-1 block

// ---------------- scratch (no allocations allowed) ----------------
__device__ float g_part[SPLIT * BB * DDIM * DDIM];   // 8 MB
__device__ float g_ksum_part[SPLIT * BB * DDIM];
__device__ float g_kv[BB * DDIM * DDIM];             // 1 MB
__device__ float g_ksum[BB * DDIM];

// ---------------- helpers ----------------
__device__ __forceinline__ unsigned long long ffma2(unsigned long long a,
                                                    unsigned long long b,
                                                    unsigned long long c) {
    unsigned long long d;
    asm("fma.rn.f32x2 %0, %1, %2, %3;" : "=l"(d) : "l"(a), "l"(b), "l"(c));
    return d;
}
__device__ __forceinline__ unsigned long long dup2(float x) {
    unsigned long long r;
    asm("mov.b64 %0, {%1, %1};" : "=l"(r) : "f"(x));
    return r;
}
__device__ __forceinline__ float2 unpk(unsigned long long v) {
    float2 f;
    asm("mov.b64 {%0, %1}, %2;" : "=f"(f.x), "=f"(f.y) : "l"(v));
    return f;
}
// feature map: elu(x)+1 = x>0 ? x+1 : exp(x)
__device__ __forceinline__ float fm(float x) {
    return x > 0.0f ? x + 1.0f : __expf(x);
}

// ---------------- phase 1: kv partials + ksum partials ----------------
__global__ __launch_bounds__(256) void phase1_kernel(const float* __restrict__ k,
                                                     const float* __restrict__ v) {
    __shared__ float kf_s[16 * 64];
    __shared__ float v_s[16 * 64];
    __shared__ float ksum_sm[64];

    const int t = threadIdx.x;
    const int sx = blockIdx.x;   // split
    const int b  = blockIdx.y;   // batch
    const int row = t >> 4;          // 0..15 (load row within chunk)
    const int c4  = (t & 15) * 4;    // 0,4,...,60 (load col)
    const int ty = t >> 4;           // d-tile 0..15
    const int tx = t & 15;           // e-tile 0..15

    const float* kp = k + ((size_t)b * SS + (size_t)sx * ROWS_P1) * DDIM;
    const float* vp = v + ((size_t)b * SS + (size_t)sx * ROWS_P1) * DDIM;

    if (t < 64) ksum_sm[t] = 0.0f;

    unsigned long long acc[4][2];
#pragma unroll
    for (int i = 0; i < 4; i++) { acc[i][0] = 0ull; acc[i][1] = 0ull; }
    float ks0 = 0.f, ks1 = 0.f, ks2 = 0.f, ks3 = 0.f;

    for (int ch = 0; ch < ROWS_P1 / 16; ch++) {
        float4 k4 = *(const float4*)(kp + (size_t)(ch * 16 + row) * DDIM + c4);
        float4 v4 = *(const float4*)(vp + (size_t)(ch * 16 + row) * DDIM + c4);
        k4.x = fm(k4.x); k4.y = fm(k4.y); k4.z = fm(k4.z); k4.w = fm(k4.w);
        ks0 += k4.x; ks1 += k4.y; ks2 += k4.z; ks3 += k4.w;

        __syncthreads();   // previous chunk fully consumed
        *(float4*)&kf_s[row * 64 + c4] = k4;
        *(float4*)&v_s[row * 64 + c4]  = v4;
        __syncthreads();

#pragma unroll
        for (int ss2 = 0; ss2 < 16; ss2++) {
            float4 a4 = *(const float4*)&kf_s[ss2 * 64 + ty * 4];
            const unsigned long long* vu =
                (const unsigned long long*)&v_s[ss2 * 64 + tx * 4];
            unsigned long long b0 = vu[0];
            unsigned long long b1 = vu[1];
            unsigned long long a;
            a = dup2(a4.x); acc[0][0] = ffma2(a, b0, acc[0][0]); acc[0][1] = ffma2(a, b1, acc[0][1]);
            a = dup2(a4.y); acc[1][0] = ffma2(a, b0, acc[1][0]); acc[1][1] = ffma2(a, b1, acc[1][1]);
            a = dup2(a4.z); acc[2][0] = ffma2(a, b0, acc[2][0]); acc[2][1] = ffma2(a, b1, acc[2][1]);
            a = dup2(a4.w); acc[3][0] = ffma2(a, b0, acc[3][0]); acc[3][1] = ffma2(a, b1, acc[3][1]);
        }
    }

    // ksum block reduction (thread loaded columns c4..c4+3 across all its rows)
    atomicAdd(&ksum_sm[c4 + 0], ks0);
    atomicAdd(&ksum_sm[c4 + 1], ks1);
    atomicAdd(&ksum_sm[c4 + 2], ks2);
    atomicAdd(&ksum_sm[c4 + 3], ks3);
    __syncthreads();

    float* outp = g_part + ((size_t)sx * BB + b) * (DDIM * DDIM);
#pragma unroll
    for (int i = 0; i < 4; i++) {
        float2 lo = unpk(acc[i][0]);
        float2 hi = unpk(acc[i][1]);
        float4 o4 = make_float4(lo.x, lo.y, hi.x, hi.y);
        *(float4*)(outp + (size_t)(ty * 4 + i) * DDIM + tx * 4) = o4;
    }
    if (t < 64) g_ksum_part[((size_t)sx * BB + b) * DDIM + t] = ksum_sm[t];
}

// ---------------- combine: sum SPLIT partials ----------------
__global__ __launch_bounds__(256) void combine_kernel() {
    const int idx = blockIdx.x * 256 + threadIdx.x;
    const int n1 = BB * DDIM * DDIM;   // 262144
    if (idx < n1) {
        float s = 0.0f;
#pragma unroll
        for (int p = 0; p < SPLIT; p++)
            s += g_part[(size_t)p * n1 + idx];
        g_kv[idx] = s;
    } else if (idx - n1 < BB * DDIM) {
        const int j = idx - n1;
        float s = 0.0f;
#pragma unroll
        for (int p = 0; p < SPLIT; p++)
            s += g_ksum_part[(size_t)p * (BB * DDIM) + j];
        g_ksum[j] = s;
    }
}

// ---------------- phase 2: o = (qf @ kv) / max(qf.ksum, 1e-4) ----------------
#define QF_STRIDE 68   // padded row stride (floats), 16B-aligned rows, breaks bank conflicts

__global__ __launch_bounds__(256) void phase2_kernel(const float* __restrict__ q,
                                                     float* __restrict__ o) {
    __shared__ float kv_s[64 * 64];          // 16 KB
    __shared__ float qf_s[64 * QF_STRIDE];   // 17 KB
    __shared__ float ksum_s[64];
    __shared__ float invden_s[64];

    const int t  = threadIdx.x;
    const int b  = blockIdx.y;
    const int s0 = blockIdx.x * 64;

    // load kv (16KB) + ksum
    const float* kvsrc = g_kv + (size_t)b * (DDIM * DDIM);
#pragma unroll
    for (int kk = 0; kk < 4; kk++) {
        int f = t + kk * 256;   // float4 index 0..1023
        *(float4*)&kv_s[f * 4] = *(const float4*)(kvsrc + (size_t)f * 4);
    }
    if (t < 64) ksum_s[t] = g_ksum[(size_t)b * DDIM + t];
    __syncthreads();

    // q load -> qf smem (+ per-row denominator via quad reduction)
    {
        const int row = t >> 2;            // 0..63
        const int qd  = (t & 3) * 16;      // d-chunk base
        const float* qp = q + ((size_t)b * SS + s0 + row) * DDIM + qd;
        float pden = 0.0f;
#pragma unroll
        for (int j = 0; j < 4; j++) {
            float4 q4 = *(const float4*)(qp + 4 * j);
            q4.x = fm(q4.x); q4.y = fm(q4.y); q4.z = fm(q4.z); q4.w = fm(q4.w);
            float4 ks = *(const float4*)&ksum_s[qd + 4 * j];
            pden += q4.x * ks.x + q4.y * ks.y + q4.z * ks.z + q4.w * ks.w;
            *(float4*)&qf_s[row * QF_STRIDE + qd + 4 * j] = q4;
        }
        pden += __shfl_xor_sync(0xffffffffu, pden, 1);
        pden += __shfl_xor_sync(0xffffffffu, pden, 2);
        if ((t & 3) == 0) invden_s[row] = 1.0f / fmaxf(pden, 1e-4f);
    }
    __syncthreads();

    const int ty = t >> 4;   // s-tile 0..15
    const int tx = t & 15;   // e-tile 0..15
    unsigned long long acc[4][2];
#pragma unroll
    for (int i = 0; i < 4; i++) { acc[i][0] = 0ull; acc[i][1] = 0ull; }

    const unsigned long long* kv_u = (const unsigned long long*)kv_s;

#define P2_STEP(DD_, COMP_)                                                        \
    {                                                                              \
        unsigned long long b0 = kv_u[(size_t)(dg + DD_) * 32 + tx * 2];            \
        unsigned long long b1 = kv_u[(size_t)(dg + DD_) * 32 + tx * 2 + 1];        \
        unsigned long long a;                                                      \
        a = dup2(qa0.COMP_); acc[0][0] = ffma2(a, b0, acc[0][0]); acc[0][1] = ffma2(a, b1, acc[0][1]); \
        a = dup2(qa1.COMP_); acc[1][0] = ffma2(a, b0, acc[1][0]); acc[1][1] = ffma2(a, b1, acc[1][1]); \
        a = dup2(qa2.COMP_); acc[2][0] = ffma2(a, b0, acc[2][0]); acc[2][1] = ffma2(a, b1, acc[2][1]); \
        a = dup2(qa3.COMP_); acc[3][0] = ffma2(a, b0, acc[3][0]); acc[3][1] = ffma2(a, b1, acc[3][1]); \
    }

#pragma unroll
    for (int dg = 0; dg < 64; dg += 4) {
        float4 qa0 = *(const float4*)&qf_s[(ty * 4 + 0) * QF_STRIDE + dg];
        float4 qa1 = *(const float4*)&qf_s[(ty * 4 + 1) * QF_STRIDE + dg];
        float4 qa2 = *(const float4*)&qf_s[(ty * 4 + 2) * QF_STRIDE + dg];
        float4 qa3 = *(const float4*)&qf_s[(ty * 4 + 3) * QF_STRIDE + dg];
        P2_STEP(0, x)
        P2_STEP(1, y)
        P2_STEP(2, z)
        P2_STEP(3, w)
    }
#undef P2_STEP

    float* op = o + ((size_t)b * SS + s0) * DDIM;
#pragma unroll
    for (int i = 0; i < 4; i++) {
        int sr = ty * 4 + i;
        float inv = invden_s[sr];
        float2 lo = unpk(acc[i][0]);
        float2 hi = unpk(acc[i][1]);
        float4 o4 = make_float4(lo.x * inv, lo.y * inv, hi.x * inv, hi.y * inv);
        *(float4*)(op + (size_t)sr * DDIM + tx * 4) = o4;
    }
}

// ---------------- launch ----------------
extern "C" void kernel_launch(void* const* d_in, const int* in_sizes, int n_in,
                              void* d_out, int out_size) {
    (void)in_sizes; (void)n_in; (void)out_size;
    const float* q = (const float*)d_in[0];
    const float* k = (const float*)d_in[1];
    const float* v = (const float*)d_in[2];
    float* o = (float*)d_out;

    dim3 g1(SPLIT, BB);
    phase1_kernel<<<g1, 256>>>(k, v);

    const int ntot = BB * DDIM * DDIM + BB * DDIM;
    combine_kernel<<<(ntot + 255) / 256, 256>>>();

    dim3 g2(SS / 64, BB);
    phase2_kernel<<<g2, 256>>>(q, o);
}